// round 4
// baseline (speedup 1.0000x reference)
#include <cuda_runtime.h>
#include <cstdint>

#define B_ 128
#define T_ 160
#define C_ 6625
#define L_ 25
#define S_ 51          // 2*L+1
#define NEGF (-1e30f)

// Scratch (no cudaMalloc allowed): lp laid out [b][t][s] so each batch's DP
// input is contiguous (32.6 KB -> fits in smem for the DP kernel).
__device__ float g_lp[(size_t)B_ * T_ * S_];
__device__ float g_loss[B_];

__device__ __forceinline__ float lae(float a, float b) {
    // log(exp(a)+exp(b)), safe for NEGF sentinels
    float mx = fmaxf(a, b);
    float mn = fminf(a, b);
    return mx + __logf(1.0f + __expf(mn - mx));
}

// ---------------------------------------------------------------------------
// Kernel 1: per (b,t) row of predicts -> logsumexp; gather extended-label
// log-probs into g_lp[b][t][s].  One block per row, row staged in registers.
// ---------------------------------------------------------------------------
__global__ __launch_bounds__(256) void k_lse_gather(
    const float* __restrict__ pred, const int* __restrict__ labels)
{
    const int row = blockIdx.x;           // row = b*T + t
    const int b   = row / T_;
    const float* __restrict__ p = pred + (size_t)row * C_;
    const int tid = threadIdx.x;

    // Stage 26 elements per thread (26*256 = 6656 >= 6625), coalesced scalar loads
    float r[26];
    float lm = -3.4e38f;
#pragma unroll
    for (int k = 0; k < 26; k++) {
        int i = tid + (k << 8);
        r[k] = (i < C_) ? __ldg(p + i) : -3.4e38f;
        lm = fmaxf(lm, r[k]);
    }

    __shared__ float sm[8];
    __shared__ float s_lse;

    // block max
    float v = lm;
#pragma unroll
    for (int o = 16; o; o >>= 1) v = fmaxf(v, __shfl_xor_sync(0xffffffffu, v, o));
    if ((tid & 31) == 0) sm[tid >> 5] = v;
    __syncthreads();
    if (tid == 0) {
        float w = sm[0];
#pragma unroll
        for (int j = 1; j < 8; j++) w = fmaxf(w, sm[j]);
        sm[0] = w;
    }
    __syncthreads();
    const float m = sm[0];

    // sum of exp
    float ls = 0.0f;
#pragma unroll
    for (int k = 0; k < 26; k++) {
        int i = tid + (k << 8);
        if (i < C_) ls += __expf(r[k] - m);
    }
    __syncthreads();   // everyone has read sm[0]; safe to reuse
#pragma unroll
    for (int o = 16; o; o >>= 1) ls += __shfl_xor_sync(0xffffffffu, ls, o);
    if ((tid & 31) == 0) sm[tid >> 5] = ls;
    __syncthreads();
    if (tid == 0) {
        float s = 0.0f;
#pragma unroll
        for (int j = 0; j < 8; j++) s += sm[j];
        s_lse = m + __logf(s);
    }
    __syncthreads();
    const float lse = s_lse;

    // gather the 51 extended-label logits (row is hot in L1)
    if (tid < S_) {
        int cls = (tid & 1) ? __ldg(labels + b * L_ + (tid >> 1)) : 0;
        g_lp[(size_t)row * S_ + tid] = p[cls] - lse;
    }
}

// ---------------------------------------------------------------------------
// Kernel 2: CTC forward DP per batch element. One block of 64 threads:
// all 64 preload lp into smem; warp 0 runs the scan with alpha[0..50]
// held as (low, high) register pairs across 32 lanes, neighbors via shfl.
// ---------------------------------------------------------------------------
__global__ __launch_bounds__(64) void k_ctc_dp(
    const int* __restrict__ labels, const int* __restrict__ lens)
{
    const int b = blockIdx.x;
    __shared__ float slp[T_ * S_];   // 32640 B
    __shared__ float sa[S_];

    const float* __restrict__ lp = g_lp + (size_t)b * T_ * S_;
    for (int i = threadIdx.x; i < T_ * S_; i += 64) slp[i] = lp[i];
    __syncthreads();
    if (threadIdx.x >= 32) return;

    const int lane = threadIdx.x;
    const unsigned FULL = 0xffffffffu;
    const int sL = lane;          // states 0..31
    const int sH = lane + 32;     // states 32..50 (lanes 19..31 carry junk NEG)

    // allow_skip: s odd, s>=3, labels[s/2] != labels[s/2 - 1]
    const int* lb = labels + b * L_;
    bool alL = false, alH = false;
    if ((sL & 1) && sL >= 3) alL = (lb[sL >> 1] != lb[(sL >> 1) - 1]);
    if ((sH & 1) && sH < S_) alH = (lb[sH >> 1] != lb[(sH >> 1) - 1]);

    // alpha init from t=0
    float aL = (lane == 0) ? slp[0] : ((lane == 1) ? slp[1] : NEGF);
    float aH = NEGF;

    for (int t = 1; t < T_; t++) {
        const float* rowp = slp + t * S_;
        float pL = rowp[sL];
        float pH = (sH < S_) ? rowp[sH] : NEGF;

        float a1L = __shfl_up_sync(FULL, aL, 1); if (lane == 0) a1L = NEGF;
        float a2L = __shfl_up_sync(FULL, aL, 2); if (lane < 2)  a2L = NEGF;
        float topL31 = __shfl_sync(FULL, aL, 31);
        float topL30 = __shfl_sync(FULL, aL, 30);
        float a1H = __shfl_up_sync(FULL, aH, 1); if (lane == 0) a1H = topL31;
        float a2H = __shfl_up_sync(FULL, aH, 2);
        if (lane == 0) a2H = topL30; else if (lane == 1) a2H = topL31;

        float nL = lae(aL, a1L); if (alL) nL = lae(nL, a2L); nL += pL;
        float nH = lae(aH, a1H); if (alH) nH = lae(nH, a2H); nH += pH;
        aL = nL; aH = nH;
    }

    sa[sL] = aL;
    if (sH < S_) sa[sH] = aH;
    __syncwarp();

    if (lane == 0) {
        int len = lens[b];
        int sl = 2 * len;                     // 20..50
        float loss = -lae(sa[sl], sa[sl - 1]);
        float w = 1.0f - __expf(-loss);       // focal weight
        g_loss[b] = loss * w * w;
    }
}

// ---------------------------------------------------------------------------
// Kernel 3: mean over batch -> scalar output
// ---------------------------------------------------------------------------
__global__ __launch_bounds__(128) void k_reduce(float* __restrict__ out)
{
    float v = g_loss[threadIdx.x];
#pragma unroll
    for (int o = 16; o; o >>= 1) v += __shfl_xor_sync(0xffffffffu, v, o);
    __shared__ float sm[4];
    if ((threadIdx.x & 31) == 0) sm[threadIdx.x >> 5] = v;
    __syncthreads();
    if (threadIdx.x == 0)
        out[0] = (sm[0] + sm[1] + sm[2] + sm[3]) * (1.0f / (float)B_);
}

extern "C" void kernel_launch(void* const* d_in, const int* in_sizes, int n_in,
                              void* d_out, int out_size)
{
    const float* pred   = (const float*)d_in[0];   // [B, T, C] fp32
    const int*   labels = (const int*)d_in[1];     // [B, L]
    const int*   lens   = (const int*)d_in[2];     // [B]
    float*       out    = (float*)d_out;           // scalar

    k_lse_gather<<<B_ * T_, 256>>>(pred, labels);
    k_ctc_dp<<<B_, 64>>>(labels, lens);
    k_reduce<<<1, 128>>>(out);
}